// round 13
// baseline (speedup 1.0000x reference)
#include <cuda_runtime.h>

// CategoryAwareGate: B=8, C=16, H=W=256, HID=32, N = B*H*W = 524288.
// d_out packing (float32): fused_logits[8,16,256,256] (8388608),
// expert_preferences[16,2] (32), dynamic_weights[N,16,2] (16777216).
//
// R13: 4 ADJACENT pixels/thread (LDG.128/STG.128), block=128, 7 CTAs/SM,
// grid=1024 == one full wave (148*7=1036 concurrent CTAs).
// Weight-LDS amortized over 4 px. dw staged in a pair-slot smem layout
// (4 slots x 516 u64, 16.5KB) with a two-phase drain (pairs 0-3 -> dw cols
// 0..15 after p=3; pairs 4-7 -> cols 16..31 after p=7), keeping smem at
// 24.8KB so 7 CTAs fit. Single d2 chain per px (4 chains of ILP).

static constexpr long FUSED_ELEMS = 8L * 16 * 65536;  // 8388608
static constexpr int SLOT_U64 = 516;  // 512 px + 4 pad (u64 units)
static constexpr int WBUF_OFF = 8256; // weights 8192 + b2diff 64
static constexpr int SMEM_BYTES = WBUF_OFF + 4 * SLOT_U64 * 8;  // 24768

__device__ __forceinline__ unsigned long long pk2(float a, float b) {
    unsigned long long r;
    asm("mov.b64 %0, {%1, %2};" : "=l"(r) : "f"(a), "f"(b));
    return r;
}
__device__ __forceinline__ void upk2(unsigned long long v, float& a, float& b) {
    asm("mov.b64 {%0, %1}, %2;" : "=f"(a), "=f"(b) : "l"(v));
}
__device__ __forceinline__ unsigned long long fma2(unsigned long long a,
                                                   unsigned long long b,
                                                   unsigned long long c) {
    unsigned long long r;
    asm("fma.rn.f32x2 %0, %1, %2, %3;" : "=l"(r) : "l"(a), "l"(b), "l"(c));
    return r;
}
// packed relu: two scalar max.f32 on the halves (no f32x2 min/max in PTX)
__device__ __forceinline__ unsigned long long relu2(unsigned long long v) {
    unsigned long long r;
    asm("{\n\t"
        ".reg .f32 lo, hi;\n\t"
        "mov.b64 {lo, hi}, %1;\n\t"
        "max.f32 lo, lo, 0f00000000;\n\t"
        "max.f32 hi, hi, 0f00000000;\n\t"
        "mov.b64 %0, {lo, hi};\n\t"
        "}" : "=l"(r) : "l"(v));
    return r;
}

__global__ void __launch_bounds__(128, 7)
gate_fuse_kernel(const float* __restrict__ swin, const float* __restrict__ gru,
                 const float* __restrict__ W1, const float* __restrict__ b1,
                 const float* __restrict__ W2, const float* __restrict__ b2,
                 float* __restrict__ fused, float* __restrict__ dw) {
    extern __shared__ __align__(16) unsigned char smem_raw[];
    unsigned long long* sw = reinterpret_cast<unsigned long long*>(smem_raw);  // 1024 u64
    float* sb2d = reinterpret_cast<float*>(smem_raw + 8192);                   // 16 floats
    unsigned long long* wbuf =
        reinterpret_cast<unsigned long long*>(smem_raw + WBUF_OFF);

    const int tid = threadIdx.x;
    const int warp = tid >> 5;
    const int lane = tid & 31;

    // Pack per-(class-pair p, h): [w10 pair][w11 pair][b1 pair][w2diff pair]
    for (int idx = tid; idx < 256; idx += 128) {
        const int p = idx >> 5, h = idx & 31;
        const int c0 = p * 2, c1 = c0 + 1;
        // W1:(C,32,2) c*64+h*2+i ; b1:(C,32) ; W2:(C,2,32) c*64+o*32+h
        sw[idx * 4 + 0] = pk2(W1[c0 * 64 + h * 2 + 0], W1[c1 * 64 + h * 2 + 0]);
        sw[idx * 4 + 1] = pk2(W1[c0 * 64 + h * 2 + 1], W1[c1 * 64 + h * 2 + 1]);
        sw[idx * 4 + 2] = pk2(b1[c0 * 32 + h], b1[c1 * 32 + h]);
        sw[idx * 4 + 3] = pk2(W2[c0 * 64 + h] - W2[c0 * 64 + 32 + h],
                              W2[c1 * 64 + h] - W2[c1 * 64 + 32 + h]);
    }
    if (tid < 16) sb2d[tid] = b2[tid * 2] - b2[tid * 2 + 1];
    __syncthreads();

    // Thread owns 4 adjacent pixels. Block = 512 consecutive px (never
    // straddles an image: 128 blocks per 65536-px image).
    const int n0 = blockIdx.x * 512 + tid * 4;
    const long base = (long)(n0 >> 16) * (16L * 65536) + (n0 & 65535);

    // Phase A: softmax denominators for 4 px (vector loads).
    float rs[4], rg[4];
    {
        float ss[4] = {0.f, 0.f, 0.f, 0.f}, sg[4] = {0.f, 0.f, 0.f, 0.f};
#pragma unroll
        for (int c = 0; c < 16; c++) {
            const float4 v = *reinterpret_cast<const float4*>(swin + base + (long)c * 65536);
            const float4 g = *reinterpret_cast<const float4*>(gru + base + (long)c * 65536);
            ss[0] += __expf(v.x); ss[1] += __expf(v.y);
            ss[2] += __expf(v.z); ss[3] += __expf(v.w);
            sg[0] += __expf(g.x); sg[1] += __expf(g.y);
            sg[2] += __expf(g.z); sg[3] += __expf(g.w);
        }
#pragma unroll
        for (int q = 0; q < 4; q++) {
            rs[q] = __fdividef(1.f, ss[q]);
            rg[q] = __fdividef(1.f, sg[q]);
        }
    }

#pragma unroll 1
    for (int p = 0; p < 8; p++) {
        const long po = base + (long)(2 * p) * 65536;
        unsigned long long xp[4], yp[4], d2[4];
        {
            const float4 A0 = *reinterpret_cast<const float4*>(swin + po);
            const float4 A1 = *reinterpret_cast<const float4*>(swin + po + 65536);
            const float4 G0 = *reinterpret_cast<const float4*>(gru + po);
            const float4 G1 = *reinterpret_cast<const float4*>(gru + po + 65536);
            const float* a0 = &A0.x; const float* a1 = &A1.x;
            const float* g0 = &G0.x; const float* g1 = &G1.x;
            const unsigned long long d2i =
                *reinterpret_cast<const unsigned long long*>(sb2d + 2 * p);
#pragma unroll
            for (int q = 0; q < 4; q++) {
                xp[q] = pk2(__expf(a0[q]) * rs[q], __expf(a1[q]) * rs[q]);
                yp[q] = pk2(__expf(g0[q]) * rg[q], __expf(g1[q]) * rg[q]);
                d2[q] = d2i;
            }
        }

        const unsigned long long* wp = sw + p * 128;
#pragma unroll
        for (int h = 0; h < 32; h++) {
            const ulonglong2 wA = *reinterpret_cast<const ulonglong2*>(wp + h * 4);
            const ulonglong2 wB = *reinterpret_cast<const ulonglong2*>(wp + h * 4 + 2);
#pragma unroll
            for (int q = 0; q < 4; q++) {
                unsigned long long t = fma2(wA.x, xp[q], wB.x);
                t = fma2(wA.y, yp[q], t);
                d2[q] = fma2(wB.y, relu2(t), d2[q]);
            }
        }

        // Sigmoids + staging + fused epilogue (logits reloaded: L1/L2 hits).
        float w0v[4], w1v[4];
#pragma unroll
        for (int q = 0; q < 4; q++) {
            float d0, d1;
            upk2(d2[q], d0, d1);
            w0v[q] = __fdividef(1.f, 1.f + __expf(-d0));
            w1v[q] = __fdividef(1.f, 1.f + __expf(-d1));
        }
        // Stage (w0,w1) u64 per px into pair-slot j = p&3 (two STS.128).
        {
            unsigned long long* slot = wbuf + (p & 3) * SLOT_U64 + tid * 4;
            *reinterpret_cast<ulonglong2*>(slot) =
                make_ulonglong2(pk2(w0v[0], w1v[0]), pk2(w0v[1], w1v[1]));
            *reinterpret_cast<ulonglong2*>(slot + 2) =
                make_ulonglong2(pk2(w0v[2], w1v[2]), pk2(w0v[3], w1v[3]));
        }
        {
            const float4 A0 = *reinterpret_cast<const float4*>(swin + po);
            const float4 A1 = *reinterpret_cast<const float4*>(swin + po + 65536);
            const float4 G0 = *reinterpret_cast<const float4*>(gru + po);
            const float4 G1 = *reinterpret_cast<const float4*>(gru + po + 65536);
            float4 F0, F1;
            F0.x = fmaf(w0v[0], A0.x - G0.x, G0.x);
            F0.y = fmaf(w0v[1], A0.y - G0.y, G0.y);
            F0.z = fmaf(w0v[2], A0.z - G0.z, G0.z);
            F0.w = fmaf(w0v[3], A0.w - G0.w, G0.w);
            F1.x = fmaf(w1v[0], A1.x - G1.x, G1.x);
            F1.y = fmaf(w1v[1], A1.y - G1.y, G1.y);
            F1.z = fmaf(w1v[2], A1.z - G1.z, G1.z);
            F1.w = fmaf(w1v[3], A1.w - G1.w, G1.w);
            *reinterpret_cast<float4*>(fused + po) = F0;
            *reinterpret_cast<float4*>(fused + po + 65536) = F1;
        }

        // Two-phase drain: after pairs 0-3 (p==3) and pairs 4-7 (p==7).
        if ((p & 3) == 3) {
            const int phase = p >> 2;
            __syncwarp();
            const long gbase = (long)blockIdx.x * 512;
#pragma unroll
            for (int k = 0; k < 16; k++) {
                const int px = warp * 128 + k * 8 + (lane >> 2);
                const int j = lane & 3;
                float w0, w1;
                upk2(wbuf[j * SLOT_U64 + px], w0, w1);
                *reinterpret_cast<float4*>(dw + (gbase + px) * 32 + phase * 16 + j * 4) =
                    make_float4(w0, 1.f - w0, w1, 1.f - w1);
            }
            __syncwarp();
        }
    }
}

extern "C" void kernel_launch(void* const* d_in, const int* in_sizes, int n_in,
                              void* d_out, int out_size) {
    const float* swin = (const float*)d_in[0];
    const float* gru  = (const float*)d_in[1];
    const float* W1   = (const float*)d_in[2];
    const float* b1   = (const float*)d_in[3];
    const float* W2   = (const float*)d_in[4];
    const float* b2   = (const float*)d_in[5];
    const float* pref = (const float*)d_in[6];

    float* out     = (float*)d_out;
    float* fusedp  = out;                     // 8388608
    float* prefout = out + FUSED_ELEMS;       // 32
    float* dwp     = out + FUSED_ELEMS + 32;  // 16777216

    cudaFuncSetAttribute(gate_fuse_kernel,
                         cudaFuncAttributeMaxDynamicSharedMemorySize, SMEM_BYTES);
    cudaMemcpyAsync(prefout, pref, 32 * sizeof(float), cudaMemcpyDeviceToDevice);
    gate_fuse_kernel<<<1024, 128, SMEM_BYTES>>>(swin, gru, W1, b1, W2, b2, fusedp, dwp);
}

// round 14
// speedup vs baseline: 1.1592x; 1.1592x over previous
#include <cuda_runtime.h>

// CategoryAwareGate: B=8, C=16, H=W=256, HID=32, N = B*H*W = 524288.
// d_out packing (float32): fused_logits[8,16,256,256] (8388608),
// expert_preferences[16,2] (32), dynamic_weights[N,16,2] (16777216).
//
// R14 = R9 (best measured kernel: ncu 59.26us) with the expert_preferences
// pass-through folded into the kernel (block 0), removing the serialized
// cudaMemcpyAsync graph node (~3-5us of wall time).
// block=128, 2 slots/thread, 7 CTAs/SM, logit-prefetch pipeline,
// smem weights, stride-18 dw staging, coalesced drain.

static constexpr long FUSED_ELEMS = 8L * 16 * 65536;  // 8388608
static constexpr int STR = 18;                         // floats per w-row
static constexpr int SMEM_BYTES = 8192 + 64 + 256 * STR * 4;  // 26688

__device__ __forceinline__ unsigned long long pk2(float a, float b) {
    unsigned long long r;
    asm("mov.b64 %0, {%1, %2};" : "=l"(r) : "f"(a), "f"(b));
    return r;
}
__device__ __forceinline__ void upk2(unsigned long long v, float& a, float& b) {
    asm("mov.b64 {%0, %1}, %2;" : "=f"(a), "=f"(b) : "l"(v));
}
__device__ __forceinline__ unsigned long long fma2(unsigned long long a,
                                                   unsigned long long b,
                                                   unsigned long long c) {
    unsigned long long r;
    asm("fma.rn.f32x2 %0, %1, %2, %3;" : "=l"(r) : "l"(a), "l"(b), "l"(c));
    return r;
}
// packed relu: two scalar max.f32 on the halves (no f32x2 min/max in PTX)
__device__ __forceinline__ unsigned long long relu2(unsigned long long v) {
    unsigned long long r;
    asm("{\n\t"
        ".reg .f32 lo, hi;\n\t"
        "mov.b64 {lo, hi}, %1;\n\t"
        "max.f32 lo, lo, 0f00000000;\n\t"
        "max.f32 hi, hi, 0f00000000;\n\t"
        "mov.b64 %0, {lo, hi};\n\t"
        "}" : "=l"(r) : "l"(v));
    return r;
}

__global__ void __launch_bounds__(128, 7)
gate_fuse_kernel(const float* __restrict__ swin, const float* __restrict__ gru,
                 const float* __restrict__ W1, const float* __restrict__ b1,
                 const float* __restrict__ W2, const float* __restrict__ b2,
                 const float* __restrict__ pref,
                 float* __restrict__ fused, float* __restrict__ dw,
                 float* __restrict__ prefout) {
    extern __shared__ __align__(16) unsigned char smem_raw[];
    unsigned long long* sw = reinterpret_cast<unsigned long long*>(smem_raw);  // 1024 u64
    float* sb2d = reinterpret_cast<float*>(smem_raw + 8192);                   // 16 floats
    float* wbuf = reinterpret_cast<float*>(smem_raw + 8192 + 64);              // 256 x 18

    const int tid = threadIdx.x;
    const int warp = tid >> 5;
    const int lane = tid & 31;

    // expert_preferences pass-through (replaces the memcpy graph node).
    if (blockIdx.x == 0 && tid < 32) prefout[tid] = pref[tid];

    // Pack per-(class-pair p, h): [w10 pair][w11 pair][b1 pair][w2diff pair]
    for (int idx = tid; idx < 256; idx += 128) {
        const int p = idx >> 5, h = idx & 31;
        const int c0 = p * 2, c1 = c0 + 1;
        // W1:(C,32,2) c*64+h*2+i ; b1:(C,32) ; W2:(C,2,32) c*64+o*32+h
        sw[idx * 4 + 0] = pk2(W1[c0 * 64 + h * 2 + 0], W1[c1 * 64 + h * 2 + 0]);
        sw[idx * 4 + 1] = pk2(W1[c0 * 64 + h * 2 + 1], W1[c1 * 64 + h * 2 + 1]);
        sw[idx * 4 + 2] = pk2(b1[c0 * 32 + h], b1[c1 * 32 + h]);
        sw[idx * 4 + 3] = pk2(W2[c0 * 64 + h] - W2[c0 * 64 + 32 + h],
                              W2[c1 * 64 + h] - W2[c1 * 64 + 32 + h]);
    }
    if (tid < 16) sb2d[tid] = b2[tid * 2] - b2[tid * 2 + 1];
    __syncthreads();

    // Block = 256 consecutive pixels (256 blocks/image: never straddles).
    const int n0 = blockIdx.x * 256 + tid;  // slot s pixel: n0 + s*128
    const long base = (long)(n0 >> 16) * (16L * 65536) + (n0 & 65535);

    // Phase A: softmax denominators (exps recomputed per pair later).
    float rs[2], rg[2];
#pragma unroll
    for (int s = 0; s < 2; s++) {
        const long bs = base + s * 128;
        float ss = 0.f, sg = 0.f;
#pragma unroll
        for (int c = 0; c < 16; c++) {
            ss += __expf(__ldg(swin + bs + (long)c * 65536));
            sg += __expf(__ldg(gru + bs + (long)c * 65536));
        }
        rs[s] = __fdividef(1.f, ss);
        rg[s] = __fdividef(1.f, sg);
    }

    float* myrow = wbuf + tid * STR;  // rows: [slot*128 + tid]

    // Prologue: load pair-0 logits. (c0 half in .x, c1 half in .y)
    float2 csl[2], cgl[2];
#pragma unroll
    for (int s = 0; s < 2; s++) {
        const long o = base + s * 128;
        csl[s] = make_float2(__ldg(swin + o), __ldg(swin + o + 65536));
        cgl[s] = make_float2(__ldg(gru + o), __ldg(gru + o + 65536));
    }

#pragma unroll 1
    for (int p = 0; p < 8; p++) {
        // Prefetch pair p+1 logits (wrap keeps it in-bounds; discarded at p=7).
        const int pn = (p + 1) & 7;
        const long pno = base + (long)(2 * pn) * 65536;
        float2 nsl[2], ngl[2];
#pragma unroll
        for (int s = 0; s < 2; s++) {
            const long o = pno + s * 128;
            nsl[s] = make_float2(__ldg(swin + o), __ldg(swin + o + 65536));
            ngl[s] = make_float2(__ldg(gru + o), __ldg(gru + o + 65536));
        }

        const unsigned long long d2i =
            *reinterpret_cast<const unsigned long long*>(sb2d + 2 * p);
        unsigned long long xp[2], yp[2], d2[2];
#pragma unroll
        for (int s = 0; s < 2; s++) {
            xp[s] = pk2(__expf(csl[s].x) * rs[s], __expf(csl[s].y) * rs[s]);
            yp[s] = pk2(__expf(cgl[s].x) * rg[s], __expf(cgl[s].y) * rg[s]);
            d2[s] = d2i;
        }

        const unsigned long long* wp = sw + p * 128;
#pragma unroll
        for (int h = 0; h < 32; h++) {
            const ulonglong2 wA = *reinterpret_cast<const ulonglong2*>(wp + h * 4);
            const ulonglong2 wB = *reinterpret_cast<const ulonglong2*>(wp + h * 4 + 2);
#pragma unroll
            for (int s = 0; s < 2; s++) {
                unsigned long long t = fma2(wA.x, xp[s], wB.x);
                t = fma2(wA.y, yp[s], t);
                d2[s] = fma2(wB.y, relu2(t), d2[s]);
            }
        }

        const long po = base + (long)(2 * p) * 65536;
#pragma unroll
        for (int s = 0; s < 2; s++) {
            float d0, d1;
            upk2(d2[s], d0, d1);
            const float w0 = __fdividef(1.f, 1.f + __expf(-d0));
            const float w1 = __fdividef(1.f, 1.f + __expf(-d1));
            *reinterpret_cast<float2*>(myrow + s * 128 * STR + 2 * p) =
                make_float2(w0, w1);
            const long o = po + s * 128;
            fused[o] = fmaf(w0, csl[s].x - cgl[s].x, cgl[s].x);
            fused[o + 65536] = fmaf(w1, csl[s].y - cgl[s].y, cgl[s].y);
            csl[s] = nsl[s];
            cgl[s] = ngl[s];
        }
    }

    __syncwarp();  // drain reads only this warp's own rows
    // Drain: per (slot, warp): 32 px * 32 floats = 4KB contiguous in dw.
#pragma unroll
    for (int s = 0; s < 2; s++) {
        const float* rows = wbuf + (s * 128 + warp * 32) * STR;
        const long g = ((long)blockIdx.x * 256 + s * 128 + warp * 32) * 32;
#pragma unroll
        for (int k = 0; k < 8; k++) {
            const int px = 4 * k + (lane >> 3);
            const int pr = lane & 7;
            const float2 w =
                *reinterpret_cast<const float2*>(rows + px * STR + pr * 2);
            *reinterpret_cast<float4*>(dw + g + k * 128 + lane * 4) =
                make_float4(w.x, 1.f - w.x, w.y, 1.f - w.y);
        }
    }
}

extern "C" void kernel_launch(void* const* d_in, const int* in_sizes, int n_in,
                              void* d_out, int out_size) {
    const float* swin = (const float*)d_in[0];
    const float* gru  = (const float*)d_in[1];
    const float* W1   = (const float*)d_in[2];
    const float* b1   = (const float*)d_in[3];
    const float* W2   = (const float*)d_in[4];
    const float* b2   = (const float*)d_in[5];
    const float* pref = (const float*)d_in[6];

    float* out     = (float*)d_out;
    float* fusedp  = out;                     // 8388608
    float* prefout = out + FUSED_ELEMS;       // 32
    float* dwp     = out + FUSED_ELEMS + 32;  // 16777216

    cudaFuncSetAttribute(gate_fuse_kernel,
                         cudaFuncAttributeMaxDynamicSharedMemorySize, SMEM_BYTES);
    gate_fuse_kernel<<<2048, 128, SMEM_BYTES>>>(swin, gru, W1, b1, W2, b2, pref,
                                                fusedp, dwp, prefout);
}